// round 10
// baseline (speedup 1.0000x reference)
#include <cuda_runtime.h>

#define NN      100000
#define EDIM    128
#define GRID    296         // 2 blocks/SM on 148 SMs — co-residency guaranteed
#define NWARPS  (GRID * 8)  // total warps

// Persistent device scratch (no allocs in kernel_launch).
__device__ float    g_a[EDIM];
__device__ float    g_part[4 * 256];     // prep partials: [chunk][col]
__device__ float2   g_T1[NN];            // (s1, s1 + s3shift)
__device__ float2   g_T2[NN];            // (s2 + bias, s2 + s3shift + bias)
__device__ int      g_partmin[GRID];     // per-block qmin partials
__device__ unsigned g_bar;               // monotonic ticket barrier (replay-safe, never reset)

__device__ __forceinline__ void grid_barrier() {
    __syncthreads();
    if (threadIdx.x == 0) {
        __threadfence();
        unsigned ticket = atomicAdd(&g_bar, 1u);
        unsigned target = (ticket / GRID + 1u) * GRID;
        while (atomicAdd(&g_bar, 0u) < target) { }
        __threadfence();
    }
    __syncthreads();
}

__global__ void __launch_bounds__(256, 2)
fused_kernel(const float* __restrict__ z, const int* __restrict__ ei,
             const float* __restrict__ z0, const float* __restrict__ Wq,
             const float* __restrict__ Wo, const float* __restrict__ bo,
             float* __restrict__ out, int N, int E) {
    __shared__ float sa[EDIM], sb[EDIM], sc[EDIM];
    __shared__ int   sred[8];
    __shared__ int   sqmin;
    const int bid  = blockIdx.x;
    const int tid  = threadIdx.x;
    const int warp = tid >> 5;
    const int lane = tid & 31;

    // ───────── Phase 1a: prep partials (blocks 0..3), coalesced, 32 LDGs in flight
    if (bid < 4) {
        __shared__ float sw[32];
        if (tid < 32) sw[tid] = Wo[EDIM + bid * 32 + tid];
        if (bid == 0 && tid >= 128) g_a[tid - 128] = Wo[tid - 128];
        __syncthreads();
        const float* base = Wq + (size_t)(bid * 32) * (2 * EDIM) + tid;
        float acc = 0.f;
        #pragma unroll
        for (int t = 0; t < 32; t++)
            acc += sw[t] * base[t * 2 * EDIM];
        g_part[bid * 256 + tid] = acc;
    }

    // ───────── Phase 1b: qmin partial sweep (all blocks), int4 pairs
    {
        int E4 = E >> 2;
        const int4* s4p = (const int4*)ei;
        const int4* d4p = (const int4*)(ei + E);
        int local = 0x7fffffff;
        int stride = GRID * 256;
        for (int i = bid * 256 + tid; i < E4; i += stride) {
            int4 s = s4p[i];
            int4 d = d4p[i];
            int m0 = max(s.x, d.x), m1 = max(s.y, d.y);
            int m2 = max(s.z, d.z), m3 = max(s.w, d.w);
            local = min(local, min(min(m0, m1), min(m2, m3)));
        }
        for (int e = (E4 << 2) + bid * 256 + tid; e < E; e += stride)
            local = min(local, max(ei[e], ei[E + e]));
        #pragma unroll
        for (int o = 16; o; o >>= 1)
            local = min(local, __shfl_xor_sync(0xffffffffu, local, o));
        if (lane == 0) sred[warp] = local;
        __syncthreads();
        if (tid == 0) {
            int v = sred[0];
            #pragma unroll
            for (int w = 1; w < 8; w++) v = min(v, sred[w]);
            g_partmin[bid] = v;          // distinct address per block
        }
    }

    grid_barrier();

    // ───────── Phase 2 prologue: fold prep partials + reduce qmin partials
    {
        float v = g_part[tid] + g_part[256 + tid] + g_part[512 + tid] + g_part[768 + tid];
        if (tid < EDIM) { sa[tid] = g_a[tid]; sb[tid] = v; }
        else            { sc[tid - EDIM] = v; }
    }
    if (warp == 7) {
        int v = 0x7fffffff;
        #pragma unroll
        for (int t = 0; t < (GRID + 31) / 32; t++) {
            int idx = lane + 32 * t;
            if (idx < GRID) v = min(v, g_partmin[idx]);
        }
        #pragma unroll
        for (int o = 16; o; o >>= 1)
            v = min(v, __shfl_xor_sync(0xffffffffu, v, o));
        if (lane == 0) sqmin = v;
    }
    __syncthreads();

    // ───────── Phase 2: node tables, 4 nodes/warp per iteration, grid-stride
    {
        const int   qmin = sqmin;
        const float bias = bo[0];
        const int   k    = lane * 4;
        const int   wg   = bid * 8 + warp;          // global warp id

        for (int node0 = wg * 4; node0 < N; node0 += NWARPS * 4) {
            float4 vz[4], w4[4];
            bool   hasw[4];
            #pragma unroll
            for (int t = 0; t < 4; t++) {
                int node = node0 + t;
                int nc   = (node < N) ? node : (N - 1);
                vz[t] = ((const float4*)(z + (size_t)nc * EDIM))[lane];
                int m = nc - qmin;
                hasw[t] = (m >= 0);
                int mc = hasw[t] ? m : 0;
                w4[t] = ((const float4*)(z0 + (size_t)mc * EDIM))[lane];
            }
            #pragma unroll
            for (int t = 0; t < 4; t++) {
                int node = node0 + t;
                float s1 = vz[t].x * sa[k] + vz[t].y * sa[k+1] + vz[t].z * sa[k+2] + vz[t].w * sa[k+3];
                float s2 = vz[t].x * sb[k] + vz[t].y * sb[k+1] + vz[t].z * sb[k+2] + vz[t].w * sb[k+3];
                float s3 = hasw[t]
                         ? (w4[t].x * sc[k] + w4[t].y * sc[k+1] + w4[t].z * sc[k+2] + w4[t].w * sc[k+3])
                         : 0.f;
                #pragma unroll
                for (int o = 16; o; o >>= 1) {
                    s1 += __shfl_xor_sync(0xffffffffu, s1, o);
                    s2 += __shfl_xor_sync(0xffffffffu, s2, o);
                    s3 += __shfl_xor_sync(0xffffffffu, s3, o);
                }
                if (lane == 0 && node < N) {
                    g_T1[node] = make_float2(s1, s1 + s3);
                    g_T2[node] = make_float2(s2 + bias, s2 + s3 + bias);
                }
            }
        }
    }

    grid_barrier();

    // ───────── Phase 3: edges, 16 per thread (two 8-edge groups)
    {
        int gtid = bid * 256 + tid;
        #pragma unroll
        for (int half = 0; half < 2; half++) {
            int base = gtid * 16 + half * 8;
            if (base + 7 < E) {
                int4 sA = *(const int4*)(ei + base);
                int4 sB = *(const int4*)(ei + base + 4);
                int4 dA = *(const int4*)(ei + E + base);
                int4 dB = *(const int4*)(ei + E + base + 4);
                int s[8] = { sA.x, sA.y, sA.z, sA.w, sB.x, sB.y, sB.z, sB.w };
                int d[8] = { dA.x, dA.y, dA.z, dA.w, dB.x, dB.y, dB.z, dB.w };
                float2 u[8], v[8];
                #pragma unroll
                for (int t = 0; t < 8; t++) u[t] = g_T1[s[t]];
                #pragma unroll
                for (int t = 0; t < 8; t++) v[t] = g_T2[d[t]];
                float r[8];
                #pragma unroll
                for (int t = 0; t < 8; t++)
                    r[t] = (s[t] >= d[t]) ? (u[t].y + v[t].x) : (u[t].x + v[t].y);
                *(float4*)(out + base)     = make_float4(r[0], r[1], r[2], r[3]);
                *(float4*)(out + base + 4) = make_float4(r[4], r[5], r[6], r[7]);
            } else {
                for (int e = base; e < E; e++) {
                    int ss = ei[e], dd = ei[E + e];
                    float2 u = g_T1[ss];
                    float2 v = g_T2[dd];
                    out[e] = (ss >= dd) ? (u.y + v.x) : (u.x + v.y);
                }
            }
        }
    }
}

extern "C" void kernel_launch(void* const* d_in, const int* in_sizes, int n_in,
                              void* d_out, int out_size) {
    // Inputs (metadata order): z, edge_index, z0, Wq, Wo, bo
    const float* z  = (const float*)d_in[0];
    const int*   ei = (const int*)d_in[1];      // jax default int32
    const float* z0 = (const float*)d_in[2];
    const float* Wq = (const float*)d_in[3];
    const float* Wo = (const float*)d_in[4];
    const float* bo = (const float*)d_in[5];
    float* out = (float*)d_out;

    int N = in_sizes[0] / EDIM;     // 100000
    int E = in_sizes[1] / 2;        // 1000000

    fused_kernel<<<GRID, 256>>>(z, ei, z0, Wq, Wo, bo, out, N, E);
}

// round 11
// speedup vs baseline: 1.4908x; 1.4908x over previous
#include <cuda_runtime.h>

#define NN      100000
#define EDIM    128
#define GRID    296                  // 2 blocks/SM on 148 SMs — co-residency guaranteed
#define TPB     512
#define WPB     (TPB / 32)           // 16 warps/block
#define NWARPS  (GRID * WPB)

// Persistent device scratch (no allocs in kernel_launch).
__device__ float    g_a[EDIM];
__device__ float    g_part[4 * 256];     // prep partials: [chunk][col]
__device__ float2   g_T1[NN];            // (s1, s1 + s3shift)
__device__ float2   g_T2[NN];            // (s2 + bias, s2 + s3shift + bias)
__device__ int      g_partmin[GRID];     // per-block qmin partials
__device__ unsigned g_bar;               // monotonic ticket barrier (replay-safe, never reset)

__device__ __forceinline__ void grid_barrier() {
    __syncthreads();
    if (threadIdx.x == 0) {
        __threadfence();
        unsigned ticket = atomicAdd(&g_bar, 1u);
        unsigned target = (ticket / GRID + 1u) * GRID;
        while (atomicAdd(&g_bar, 0u) < target) { }
        __threadfence();
    }
    __syncthreads();
}

__global__ void __launch_bounds__(TPB, 2)
fused_kernel(const float* __restrict__ z, const int* __restrict__ ei,
             const float* __restrict__ z0, const float* __restrict__ Wq,
             const float* __restrict__ Wo, const float* __restrict__ bo,
             float* __restrict__ out, int N, int E) {
    __shared__ float sa[EDIM], sb[EDIM], sc[EDIM];
    __shared__ int   sred[WPB];
    __shared__ int   sqmin;
    const int bid  = blockIdx.x;
    const int tid  = threadIdx.x;
    const int warp = tid >> 5;
    const int lane = tid & 31;

    // ───────── Phase 1a: prep partials (blocks 0..3; first 256 threads), coalesced
    if (bid < 4 && tid < 256) {
        __shared__ float sw[32];
        if (tid < 32) sw[tid] = Wo[EDIM + bid * 32 + tid];
        if (bid == 0 && tid >= 128) g_a[tid - 128] = Wo[tid - 128];
        __syncwarp();
        __syncthreads();
        const float* base = Wq + (size_t)(bid * 32) * (2 * EDIM) + tid;
        float acc = 0.f;
        #pragma unroll
        for (int t = 0; t < 32; t++)
            acc += sw[t] * base[t * 2 * EDIM];
        g_part[bid * 256 + tid] = acc;
    } else if (bid < 4) {
        __syncthreads();                    // pair with the syncthreads above
    }

    // ───────── Phase 1b: qmin partial sweep (all blocks), int4 pairs
    {
        int E4 = E >> 2;
        const int4* s4p = (const int4*)ei;
        const int4* d4p = (const int4*)(ei + E);
        int local = 0x7fffffff;
        int stride = GRID * TPB;
        for (int i = bid * TPB + tid; i < E4; i += stride) {
            int4 s = s4p[i];
            int4 d = d4p[i];
            int m0 = max(s.x, d.x), m1 = max(s.y, d.y);
            int m2 = max(s.z, d.z), m3 = max(s.w, d.w);
            local = min(local, min(min(m0, m1), min(m2, m3)));
        }
        for (int e = (E4 << 2) + bid * TPB + tid; e < E; e += stride)
            local = min(local, max(ei[e], ei[E + e]));
        #pragma unroll
        for (int o = 16; o; o >>= 1)
            local = min(local, __shfl_xor_sync(0xffffffffu, local, o));
        if (lane == 0) sred[warp] = local;
        __syncthreads();
        if (tid == 0) {
            int v = sred[0];
            #pragma unroll
            for (int w = 1; w < WPB; w++) v = min(v, sred[w]);
            g_partmin[bid] = v;             // distinct address per block
        }
    }

    grid_barrier();

    // ───────── Phase 2 prologue: fold prep partials + reduce qmin partials
    if (tid < 256) {
        float v = g_part[tid] + g_part[256 + tid] + g_part[512 + tid] + g_part[768 + tid];
        if (tid < EDIM) { sa[tid] = g_a[tid]; sb[tid] = v; }
        else            { sc[tid - EDIM] = v; }
    }
    if (warp == WPB - 1) {
        int v = 0x7fffffff;
        #pragma unroll
        for (int t = 0; t < (GRID + 31) / 32; t++) {
            int idx = lane + 32 * t;
            if (idx < GRID) v = min(v, g_partmin[idx]);
        }
        #pragma unroll
        for (int o = 16; o; o >>= 1)
            v = min(v, __shfl_xor_sync(0xffffffffu, v, o));
        if (lane == 0) sqmin = v;
    }
    __syncthreads();

    // ───────── Phase 2: node tables, 4 nodes/warp per iteration, grid-stride
    {
        const int   qmin = sqmin;
        const float bias = bo[0];
        const int   k    = lane * 4;
        const int   wg   = bid * WPB + warp;        // global warp id

        for (int node0 = wg * 4; node0 < N; node0 += NWARPS * 4) {
            float4 vz[4], w4[4];
            bool   hasw[4];
            #pragma unroll
            for (int t = 0; t < 4; t++) {
                int node = node0 + t;
                int nc   = (node < N) ? node : (N - 1);
                vz[t] = ((const float4*)(z + (size_t)nc * EDIM))[lane];
                int m = nc - qmin;
                hasw[t] = (m >= 0);
                int mc = hasw[t] ? m : 0;
                w4[t] = ((const float4*)(z0 + (size_t)mc * EDIM))[lane];
            }
            #pragma unroll
            for (int t = 0; t < 4; t++) {
                int node = node0 + t;
                float s1 = vz[t].x * sa[k] + vz[t].y * sa[k+1] + vz[t].z * sa[k+2] + vz[t].w * sa[k+3];
                float s2 = vz[t].x * sb[k] + vz[t].y * sb[k+1] + vz[t].z * sb[k+2] + vz[t].w * sb[k+3];
                float s3 = hasw[t]
                         ? (w4[t].x * sc[k] + w4[t].y * sc[k+1] + w4[t].z * sc[k+2] + w4[t].w * sc[k+3])
                         : 0.f;
                #pragma unroll
                for (int o = 16; o; o >>= 1) {
                    s1 += __shfl_xor_sync(0xffffffffu, s1, o);
                    s2 += __shfl_xor_sync(0xffffffffu, s2, o);
                    s3 += __shfl_xor_sync(0xffffffffu, s3, o);
                }
                if (lane == 0 && node < N) {
                    g_T1[node] = make_float2(s1, s1 + s3);
                    g_T2[node] = make_float2(s2 + bias, s2 + s3 + bias);
                }
            }
        }
    }

    grid_barrier();

    // ───────── Phase 3: edges, 8 per thread (16 gathers in flight)
    {
        int base = (bid * TPB + tid) * 8;
        if (base + 7 < E) {
            int4 sA = *(const int4*)(ei + base);
            int4 sB = *(const int4*)(ei + base + 4);
            int4 dA = *(const int4*)(ei + E + base);
            int4 dB = *(const int4*)(ei + E + base + 4);
            int s[8] = { sA.x, sA.y, sA.z, sA.w, sB.x, sB.y, sB.z, sB.w };
            int d[8] = { dA.x, dA.y, dA.z, dA.w, dB.x, dB.y, dB.z, dB.w };
            float2 u[8], v[8];
            #pragma unroll
            for (int t = 0; t < 8; t++) u[t] = g_T1[s[t]];
            #pragma unroll
            for (int t = 0; t < 8; t++) v[t] = g_T2[d[t]];
            float r[8];
            #pragma unroll
            for (int t = 0; t < 8; t++)
                r[t] = (s[t] >= d[t]) ? (u[t].y + v[t].x) : (u[t].x + v[t].y);
            *(float4*)(out + base)     = make_float4(r[0], r[1], r[2], r[3]);
            *(float4*)(out + base + 4) = make_float4(r[4], r[5], r[6], r[7]);
        } else {
            for (int e = base; e < E; e++) {
                int ss = ei[e], dd = ei[E + e];
                float2 u = g_T1[ss];
                float2 v = g_T2[dd];
                out[e] = (ss >= dd) ? (u.y + v.x) : (u.x + v.y);
            }
        }
    }
}

extern "C" void kernel_launch(void* const* d_in, const int* in_sizes, int n_in,
                              void* d_out, int out_size) {
    // Inputs (metadata order): z, edge_index, z0, Wq, Wo, bo
    const float* z  = (const float*)d_in[0];
    const int*   ei = (const int*)d_in[1];      // jax default int32
    const float* z0 = (const float*)d_in[2];
    const float* Wq = (const float*)d_in[3];
    const float* Wo = (const float*)d_in[4];
    const float* bo = (const float*)d_in[5];
    float* out = (float*)d_out;

    int N = in_sizes[0] / EDIM;     // 100000
    int E = in_sizes[1] / 2;        // 1000000

    fused_kernel<<<GRID, TPB>>>(z, ei, z0, Wq, Wo, bo, out, N, E);
}